// round 16
// baseline (speedup 1.0000x reference)
#include <cuda_runtime.h>
#include <cuda_bf16.h>
#include <math.h>
#include <stdint.h>

#define N_  50000
#define E_  512000
#define IN_ 512
#define H_  128
#define NH_ (N_*H_)
#define DT_   0.1f
#define EPS_  1e-3f
#define TOL_  1e-4f
#define MAXIT_ 20
#define CGRID_ 444

// ---------------- device scratch ----------------
__device__ __align__(16) float g_h[NH_];
__device__ __align__(16) float g_hs[NH_];
__device__ __align__(16) float g_X[NH_];
__device__ __align__(16) float g_R[NH_];
__device__ __align__(16) float g_P[NH_];
__device__ __align__(16) float g_AP[NH_];
__device__ __align__(16) float g_F[NH_];
__device__ __align__(16) __nv_bfloat162 g_Pb[NH_ / 2];
__device__ __align__(16) __nv_bfloat162 g_hb[NH_ / 2];
__device__ __align__(16) __nv_bfloat162 g_Rb[NH_ / 2];
__device__ float g_wL[E_];
__device__ float g_rown[N_];
__device__ float g_deg[N_];
__device__ float g_isd[N_];
__device__ int   g_cnt[N_];
__device__ int   g_ptr[N_ + 1];
__device__ int   g_adj[2 * E_];
__device__ float g_adjw[2 * E_];
__device__ float g_adjw2[2 * E_];
__device__ int   g_incnt[N_];
__device__ int   g_inptr[N_ + 1];
__device__ int   g_insrc[E_ + N_];
__device__ float g_rsA[MAXIT_ + 1][H_];
__device__ float g_denA[MAXIT_][H_];
__device__ int   g_barc;
__device__ volatile int g_barp;
__device__ float g_aq[4];
__device__ __align__(16) float g_xw1[N_ * 64];
__device__ float g_es1[N_ * 8], g_ed1[N_ * 8];
__device__ __align__(16) float g_o1[N_ * 64];
__device__ __align__(16) float g_xw2[N_ * 16];
__device__ float g_es2[N_], g_ed2[N_];

// ---------------- tf32 / cp.async / bf16 helpers ----------------
__device__ __forceinline__ uint32_t f2tf32(float f)
{
    uint32_t u;
    asm("cvt.rna.tf32.f32 %0, %1;" : "=r"(u) : "f"(f));
    return u;
}
__device__ __forceinline__ void mma_tf32(float* c, const uint32_t* a, uint32_t b0, uint32_t b1)
{
    asm volatile(
        "mma.sync.aligned.m16n8k8.row.col.f32.tf32.tf32.f32 "
        "{%0,%1,%2,%3}, {%4,%5,%6,%7}, {%8,%9}, {%0,%1,%2,%3};\n"
        : "+f"(c[0]), "+f"(c[1]), "+f"(c[2]), "+f"(c[3])
        : "r"(a[0]), "r"(a[1]), "r"(a[2]), "r"(a[3]), "r"(b0), "r"(b1));
}
__device__ __forceinline__ void cpa16(uint32_t d, const float* s, int ok)
{
    asm volatile("cp.async.ca.shared.global [%0], [%1], 16, %2;\n"
                 :: "r"(d), "l"(s), "r"(ok ? 16 : 0));
}
#define CP_COMMIT() asm volatile("cp.async.commit_group;\n" ::)
#define CP_WAIT1()  asm volatile("cp.async.wait_group 1;\n" ::)
#define CP_WAIT0()  asm volatile("cp.async.wait_group 0;\n" ::)

__device__ __forceinline__ uint2 pack4(float4 v)
{
    __nv_bfloat162 a = __floats2bfloat162_rn(v.x, v.y);
    __nv_bfloat162 b = __floats2bfloat162_rn(v.z, v.w);
    uint2 r;
    r.x = *(uint32_t*)&a; r.y = *(uint32_t*)&b;
    return r;
}
__device__ __forceinline__ float4 unpack4(uint2 raw)
{
    __nv_bfloat162 b0 = *(__nv_bfloat162*)&raw.x;
    __nv_bfloat162 b1 = *(__nv_bfloat162*)&raw.y;
    float2 lo = __bfloat1622float2(b0);
    float2 hi = __bfloat1622float2(b1);
    return make_float4(lo.x, lo.y, hi.x, hi.y);
}

// pipelined 128x128 tf32 mainloop; A row-major [*,K], B row-major [K,128]
template<int K>
__device__ __forceinline__ void tf32_loop(const float* __restrict__ A,
    const float* __restrict__ B, int m0, float acc[2][8][4],
    float* As, float* Bs)
{
    int tid = threadIdx.x, lane = tid & 31, wid = tid >> 5;
    int wm = wid & 3, wn = wid >> 2;
    int gid = lane >> 2, ctid = lane & 3;
    uint32_t asb = (uint32_t)__cvta_generic_to_shared(As);
    uint32_t bsb = (uint32_t)__cvta_generic_to_shared(Bs);
    const int ABUF = 128 * 20 * 4, BBUF = 16 * 132 * 4;
    int ar0 = tid >> 2, ak0 = tid & 3;
    int ar1 = (tid + 256) >> 2, ak1 = (tid + 256) & 3;
    int br0 = tid >> 5, bc0 = tid & 31;
    int br1 = (tid + 256) >> 5, bc1 = (tid + 256) & 31;

    cpa16(asb + (ar0 * 20 + ak0 * 4) * 4, A + (size_t)(m0 + ar0) * K + ak0 * 4, m0 + ar0 < N_);
    cpa16(asb + (ar1 * 20 + ak1 * 4) * 4, A + (size_t)(m0 + ar1) * K + ak1 * 4, m0 + ar1 < N_);
    cpa16(bsb + (br0 * 132 + bc0 * 4) * 4, B + (size_t)br0 * H_ + bc0 * 4, 1);
    cpa16(bsb + (br1 * 132 + bc1 * 4) * 4, B + (size_t)br1 * H_ + bc1 * 4, 1);
    CP_COMMIT();

    const int NC = K / 16;
    for (int c = 0; c < NC; c++) {
        int buf = c & 1;
        if (c + 1 < NC) {
            int k0 = (c + 1) * 16, nb = buf ^ 1;
            cpa16(asb + nb * ABUF + (ar0 * 20 + ak0 * 4) * 4, A + (size_t)(m0 + ar0) * K + k0 + ak0 * 4, m0 + ar0 < N_);
            cpa16(asb + nb * ABUF + (ar1 * 20 + ak1 * 4) * 4, A + (size_t)(m0 + ar1) * K + k0 + ak1 * 4, m0 + ar1 < N_);
            cpa16(bsb + nb * BBUF + (br0 * 132 + bc0 * 4) * 4, B + (size_t)(k0 + br0) * H_ + bc0 * 4, 1);
            cpa16(bsb + nb * BBUF + (br1 * 132 + bc1 * 4) * 4, B + (size_t)(k0 + br1) * H_ + bc1 * 4, 1);
            CP_COMMIT();
            CP_WAIT1();
        } else {
            CP_WAIT0();
        }
        __syncthreads();
        const float* Af = As + buf * (128 * 20);
        const float* Bf = Bs + buf * (16 * 132);
#pragma unroll
        for (int k8 = 0; k8 < 16; k8 += 8) {
            uint32_t a[2][4];
#pragma unroll
            for (int mt = 0; mt < 2; mt++) {
                int r0 = wm * 32 + mt * 16 + gid;
                a[mt][0] = f2tf32(Af[r0 * 20 + k8 + ctid]);
                a[mt][1] = f2tf32(Af[(r0 + 8) * 20 + k8 + ctid]);
                a[mt][2] = f2tf32(Af[r0 * 20 + k8 + ctid + 4]);
                a[mt][3] = f2tf32(Af[(r0 + 8) * 20 + k8 + ctid + 4]);
            }
#pragma unroll
            for (int nt = 0; nt < 8; nt++) {
                int col = wn * 64 + nt * 8 + gid;
                uint32_t b0 = f2tf32(Bf[(k8 + ctid) * 132 + col]);
                uint32_t b1 = f2tf32(Bf[(k8 + ctid + 4) * 132 + col]);
                mma_tf32(acc[0][nt], a[0], b0, b1);
                mma_tf32(acc[1][nt], a[1], b0, b1);
            }
        }
        __syncthreads();
    }
}

// -------- GEMM1 tf32 + fused bias + LayerNorm + sigmoid -> g_h --------
__global__ __launch_bounds__(256) void gemm_lnsig_tf32_k(const float* __restrict__ A,
    const float* __restrict__ B, const float* __restrict__ bias,
    const float* __restrict__ lng, const float* __restrict__ lnb)
{
    __shared__ float As[2 * 128 * 20];
    __shared__ float Bs[2 * 16 * 132];
    __shared__ float ssum[128], ssq[128];
    int tid = threadIdx.x, lane = tid & 31, wid = tid >> 5;
    int wm = wid & 3, wn = wid >> 2;
    int gid = lane >> 2, ctid = lane & 3;
    int m0 = blockIdx.x * 128;
    float acc[2][8][4];
#pragma unroll
    for (int mt = 0; mt < 2; mt++)
#pragma unroll
        for (int nt = 0; nt < 8; nt++)
#pragma unroll
            for (int c = 0; c < 4; c++) acc[mt][nt][c] = 0.f;

    tf32_loop<IN_>(A, B, m0, acc, As, Bs);

    float b2[8][2], gg[8][2], bb[8][2];
#pragma unroll
    for (int nt = 0; nt < 8; nt++) {
        int col = wn * 64 + nt * 8 + 2 * ctid;
        b2[nt][0] = bias[col]; b2[nt][1] = bias[col + 1];
        gg[nt][0] = lng[col];  gg[nt][1] = lng[col + 1];
        bb[nt][0] = lnb[col];  bb[nt][1] = lnb[col + 1];
    }
    if (tid < 128) { ssum[tid] = 0.f; ssq[tid] = 0.f; }
    __syncthreads();
#pragma unroll
    for (int mt = 0; mt < 2; mt++)
#pragma unroll
        for (int half = 0; half < 2; half++) {
            int r = wm * 32 + mt * 16 + gid + 8 * half;
            float s = 0.f;
#pragma unroll
            for (int nt = 0; nt < 8; nt++)
                s += (acc[mt][nt][2 * half] + b2[nt][0]) + (acc[mt][nt][2 * half + 1] + b2[nt][1]);
            atomicAdd(&ssum[r], s);
        }
    __syncthreads();
#pragma unroll
    for (int mt = 0; mt < 2; mt++)
#pragma unroll
        for (int half = 0; half < 2; half++) {
            int r = wm * 32 + mt * 16 + gid + 8 * half;
            float mean = ssum[r] * (1.f / 128.f);
            float q = 0.f;
#pragma unroll
            for (int nt = 0; nt < 8; nt++) {
                float d0 = acc[mt][nt][2 * half] + b2[nt][0] - mean;
                float d1 = acc[mt][nt][2 * half + 1] + b2[nt][1] - mean;
                q += d0 * d0 + d1 * d1;
            }
            atomicAdd(&ssq[r], q);
        }
    __syncthreads();
#pragma unroll
    for (int mt = 0; mt < 2; mt++)
#pragma unroll
        for (int half = 0; half < 2; half++) {
            int r = wm * 32 + mt * 16 + gid + 8 * half;
            if (m0 + r >= N_) continue;
            float mean = ssum[r] * (1.f / 128.f);
            float rstd = rsqrtf(ssq[r] * (1.f / 128.f) + 1e-5f);
#pragma unroll
            for (int nt = 0; nt < 8; nt++) {
                int col = wn * 64 + nt * 8 + 2 * ctid;
                float u0 = (acc[mt][nt][2 * half]     + b2[nt][0] - mean) * rstd * gg[nt][0] + bb[nt][0];
                float u1 = (acc[mt][nt][2 * half + 1] + b2[nt][1] - mean) * rstd * gg[nt][1] + bb[nt][1];
                float2 o;
                o.x = 1.f / (1.f + expf(-u0));
                o.y = 1.f / (1.f + expf(-u1));
                *(float2*)(g_h + (size_t)(m0 + r) * H_ + col) = o;
            }
        }
}

// -------- sheaf GEMM tf32: g_hs = g_h @ W_sh, + row norms g_rown --------
__global__ __launch_bounds__(256) void gemm_sheaf_tf32_k(const float* __restrict__ B)
{
    __shared__ float As[2 * 128 * 20];
    __shared__ float Bs[2 * 16 * 132];
    __shared__ float rsum[128];
    int tid = threadIdx.x, lane = tid & 31, wid = tid >> 5;
    int wm = wid & 3, wn = wid >> 2;
    int gid = lane >> 2, ctid = lane & 3;
    int m0 = blockIdx.x * 128;
    float acc[2][8][4];
#pragma unroll
    for (int mt = 0; mt < 2; mt++)
#pragma unroll
        for (int nt = 0; nt < 8; nt++)
#pragma unroll
            for (int c = 0; c < 4; c++) acc[mt][nt][c] = 0.f;

    tf32_loop<H_>(g_h, B, m0, acc, As, Bs);

    if (tid < 128) rsum[tid] = 0.f;
    __syncthreads();
#pragma unroll
    for (int mt = 0; mt < 2; mt++)
#pragma unroll
        for (int half = 0; half < 2; half++) {
            int r = wm * 32 + mt * 16 + gid + 8 * half;
            float q = 0.f;
#pragma unroll
            for (int nt = 0; nt < 8; nt++) {
                float v0 = acc[mt][nt][2 * half], v1 = acc[mt][nt][2 * half + 1];
                q += v0 * v0 + v1 * v1;
                if (m0 + r < N_) {
                    int col = wn * 64 + nt * 8 + 2 * ctid;
                    float2 o; o.x = v0; o.y = v1;
                    *(float2*)(g_hs + (size_t)(m0 + r) * H_ + col) = o;
                }
            }
            atomicAdd(&rsum[r], q);
        }
    __syncthreads();
    if (tid < 128 && m0 + tid < N_) g_rown[m0 + tid] = rsum[tid];
}

// -------- gat1 GEMM tf32: xw1 = F @ W1 + es/ed --------
__global__ __launch_bounds__(256) void gemm_gat1_tf32_k(const float* __restrict__ B,
    const float* __restrict__ a1s, const float* __restrict__ a1d)
{
    __shared__ uint32_t As[128 * 36];
    __shared__ uint32_t Bs[32 * 68];
    int tid = threadIdx.x, lane = tid & 31, wid = tid >> 5;
    int gid = lane >> 2, ctid = lane & 3;
    int m0 = blockIdx.x * 128;
    float acc[8][4];
#pragma unroll
    for (int nt = 0; nt < 8; nt++)
#pragma unroll
        for (int c = 0; c < 4; c++) acc[nt][c] = 0.f;

    for (int k0 = 0; k0 < 128; k0 += 32) {
#pragma unroll
        for (int i = 0; i < 4; i++) {
            int f4 = tid + i * 256;
            int row = f4 >> 3, kq = f4 & 7;
            float4 v = make_float4(0.f, 0.f, 0.f, 0.f);
            if (m0 + row < N_) v = *(const float4*)(g_F + (size_t)(m0 + row) * H_ + k0 + kq * 4);
            uint32_t* d = &As[row * 36 + kq * 4];
            d[0] = f2tf32(v.x); d[1] = f2tf32(v.y); d[2] = f2tf32(v.z); d[3] = f2tf32(v.w);
        }
#pragma unroll
        for (int i = 0; i < 2; i++) {
            int f4 = tid + i * 256;
            int kr = f4 >> 4, cq = f4 & 15;
            float4 v = *(const float4*)(B + (size_t)(k0 + kr) * 64 + cq * 4);
            uint32_t* d = &Bs[kr * 68 + cq * 4];
            d[0] = f2tf32(v.x); d[1] = f2tf32(v.y); d[2] = f2tf32(v.z); d[3] = f2tf32(v.w);
        }
        __syncthreads();
#pragma unroll
        for (int k8 = 0; k8 < 32; k8 += 8) {
            uint32_t a[4];
            int r0 = wid * 16 + gid;
            a[0] = As[r0 * 36 + k8 + ctid];
            a[1] = As[(r0 + 8) * 36 + k8 + ctid];
            a[2] = As[r0 * 36 + k8 + ctid + 4];
            a[3] = As[(r0 + 8) * 36 + k8 + ctid + 4];
#pragma unroll
            for (int nt = 0; nt < 8; nt++) {
                int col = nt * 8 + gid;
                uint32_t b0 = Bs[(k8 + ctid) * 68 + col];
                uint32_t b1 = Bs[(k8 + ctid + 4) * 68 + col];
                mma_tf32(acc[nt], a, b0, b1);
            }
        }
        __syncthreads();
    }
    float as[8][2], ad[8][2];
#pragma unroll
    for (int nt = 0; nt < 8; nt++) {
        int c = nt * 8 + 2 * ctid;
        as[nt][0] = a1s[c]; as[nt][1] = a1s[c + 1];
        ad[nt][0] = a1d[c]; ad[nt][1] = a1d[c + 1];
    }
#pragma unroll
    for (int half = 0; half < 2; half++) {
        int r = wid * 16 + gid + 8 * half;
        bool ok = (m0 + r < N_);
#pragma unroll
        for (int nt = 0; nt < 8; nt++) {
            float v0 = acc[nt][2 * half], v1 = acc[nt][2 * half + 1];
            if (ok) {
                float2 o; o.x = v0; o.y = v1;
                *(float2*)(g_xw1 + (size_t)(m0 + r) * 64 + nt * 8 + 2 * ctid) = o;
            }
            float es = v0 * as[nt][0] + v1 * as[nt][1];
            float ed = v0 * ad[nt][0] + v1 * ad[nt][1];
            es += __shfl_xor_sync(~0u, es, 1); es += __shfl_xor_sync(~0u, es, 2);
            ed += __shfl_xor_sync(~0u, ed, 1); ed += __shfl_xor_sync(~0u, ed, 2);
            if (ok && ctid == 0) {
                g_es1[(size_t)(m0 + r) * 8 + nt] = es;
                g_ed1[(size_t)(m0 + r) * 8 + nt] = ed;
            }
        }
    }
}

// -------- xw2 = o1 @ W2 + fused es2/ed2 --------
__global__ __launch_bounds__(256) void xw2_coeff_k(const float* __restrict__ W2,
    const float* __restrict__ a2s, const float* __restrict__ a2d)
{
    __shared__ float W2s[64][17];
    int tid = threadIdx.x;
    for (int i = tid; i < 64 * 16; i += 256)
        W2s[i >> 4][i & 15] = W2[i];
    __syncthreads();
    int wid = tid >> 5, lane = tid & 31;
    int sub = lane >> 4;
    int col = lane & 15;
    int node = blockIdx.x * 16 + wid * 2 + sub;
    if (node >= N_) return;
    const float* o1 = g_o1 + (size_t)node * 64;
    float acc = 0.f;
#pragma unroll
    for (int k4 = 0; k4 < 64; k4 += 4) {
        float4 v = *(const float4*)(o1 + k4);
        acc += v.x * W2s[k4][col] + v.y * W2s[k4 + 1][col]
             + v.z * W2s[k4 + 2][col] + v.w * W2s[k4 + 3][col];
    }
    g_xw2[(size_t)node * 16 + col] = acc;
    float es = acc * a2s[col], ed = acc * a2d[col];
#pragma unroll
    for (int o = 8; o; o >>= 1) {
        es += __shfl_xor_sync(~0u, es, o);
        ed += __shfl_xor_sync(~0u, ed, o);
    }
    if (col == 0) { g_es2[node] = es; g_ed2[node] = ed; }
}

// -------- edge weights (dot + row norms) + degree + CSR counts --------
__global__ void edge_w_k(const int* __restrict__ row, const int* __restrict__ col)
{
    int w = threadIdx.x >> 5, lane = threadIdx.x & 31;
    int e0 = blockIdx.x * 32 + w * 4;
#pragma unroll
    for (int k = 0; k < 4; k++) {
        int e = e0 + k;
        if (e >= E_) return;
        int r = row[e], c = col[e];
        float4 a = *(const float4*)(g_hs + ((size_t)r << 7) + (lane << 2));
        float4 b = *(const float4*)(g_hs + ((size_t)c << 7) + (lane << 2));
        float dot = a.x * b.x + a.y * b.y + a.z * b.z + a.w * b.w;
#pragma unroll
        for (int o = 16; o; o >>= 1)
            dot += __shfl_xor_sync(~0u, dot, o);
        if (lane == 0) {
            float sa = g_rown[r];
            float sd = fmaxf(sa + g_rown[c] - 2.f * dot, 0.f);
            float C  = sd * (1.f / 128.f);
            float ex = expf(-C * (1.f / EPS_));
            float P0 = fminf(fmaxf(ex, 1e-3f), 1.f);
            float Ps = fminf(fmaxf((P0 + 1e-12f) * ex, 1e-3f), 1.f);
            float ww = 0.7f * P0 + 0.3f * Ps;
            float wl = ww * ww * sa * (1.f / 128.f);
            g_wL[e] = wl;
            atomicAdd(&g_deg[r], wl);
            atomicAdd(&g_deg[c], wl);
            atomicAdd(&g_cnt[r], 1);
            atomicAdd(&g_cnt[c], 1);
            atomicAdd(&g_incnt[c], 1);
        }
    }
}

// ---------------- CSR build ----------------
__global__ void zero3_k()
{
    int i = blockIdx.x * blockDim.x + threadIdx.x;
    if (i < N_) { g_deg[i] = 0.f; g_cnt[i] = 0; g_incnt[i] = 0; }
}
__device__ __forceinline__ void scan_body(int* cnt, int* ptr, int n, int selfpad, int* sh)
{
    int t = threadIdx.x;
    int chunk = (n + 1023) / 1024;
    int lo = t * chunk, hi = min(lo + chunk, n);
    if (lo > n) lo = n;
    int s = 0;
    for (int i = lo; i < hi; i++) s += cnt[i];
    sh[t] = s;
    __syncthreads();
    for (int off = 1; off < 1024; off <<= 1) {
        int v = (t >= off) ? sh[t - off] : 0;
        __syncthreads();
        sh[t] += v;
        __syncthreads();
    }
    int run = sh[t] - s;
    for (int i = lo; i < hi; i++) {
        int c = cnt[i];
        int base = run + selfpad * i;
        ptr[i] = base; cnt[i] = base; run += c;
    }
    if (t == 1023) ptr[n] = sh[1023] + selfpad * n;
    __syncthreads();
}
__global__ void scan2_k()
{
    __shared__ int sh[1024];
    scan_body(g_cnt, g_ptr, N_, 0, sh);
    scan_body(g_incnt, g_inptr, N_, 1, sh);
    int t = threadIdx.x;
    float* rs = &g_rsA[0][0];
    float* dn = &g_denA[0][0];
    for (int i = t; i < (MAXIT_ + 1) * H_; i += 1024) rs[i] = 0.f;
    for (int i = t; i < MAXIT_ * H_; i += 1024) dn[i] = 0.f;
    if (t == 0) { g_barc = 0; g_barp = 0; }
}
__global__ void scatter_adj_k(const int* __restrict__ row, const int* __restrict__ col)
{
    int e = blockIdx.x * blockDim.x + threadIdx.x;
    if (e >= E_) return;
    int r = row[e], c = col[e];
    float w = g_wL[e];
    int p = atomicAdd(&g_cnt[r], 1); g_adj[p] = c; g_adjw[p] = w;
    int q = atomicAdd(&g_cnt[c], 1); g_adj[q] = r; g_adjw[q] = w;
}
__global__ void scatter_in_self_k(const int* __restrict__ row, const int* __restrict__ col)
{
    int i = blockIdx.x * blockDim.x + threadIdx.x;
    if (i < E_) {
        int p = atomicAdd(&g_incnt[col[i]], 1);
        g_insrc[p] = row[i];
    } else if (i < E_ + N_) {
        int n = i - E_;
        int p = atomicAdd(&g_incnt[n], 1);
        g_insrc[p] = n;
    }
}

// ---------------- grid barrier ----------------
__device__ __forceinline__ void gridbar()
{
    __threadfence();
    __syncthreads();
    if (threadIdx.x == 0) {
        int ph = g_barp;
        if (atomicAdd(&g_barc, 1) == (int)gridDim.x - 1) {
            g_barc = 0;
            __threadfence();
            g_barp = ph ^ 1;
        } else {
            while (g_barp == ph) __nanosleep(32);
        }
    }
    __syncthreads();
}

// ---------------- merged persistent CG + AFM (bf16 gathers) ----------------
__device__ __forceinline__ void tildeL_phase(const float* __restrict__ M,
    const __nv_bfloat162* __restrict__ Mb, const float* __restrict__ Mp,
    float* __restrict__ out, __nv_bfloat162* __restrict__ outb, float cA, float cB)
{
    int lane = threadIdx.x & 31, wid = threadIdx.x >> 5;
    int gwarp = blockIdx.x * 8 + wid, nwarp = gridDim.x * 8;
    for (int wc = gwarp; wc < N_ / 4; wc += nwarp) {
#pragma unroll
        for (int k = 0; k < 4; k++) {
            int node = wc * 4 + k;
            int j0 = g_ptr[node], j1 = g_ptr[node + 1];
            float4 a = make_float4(0.f, 0.f, 0.f, 0.f);
            for (int j = j0; j < j1; j++) {
                int nb = g_adj[j];
                float wv = g_adjw2[j];
                uint2 raw = __ldcg((const uint2*)Mb + ((size_t)nb << 5) + lane);
                float4 v = unpack4(raw);
                a.x += wv * v.x; a.y += wv * v.y; a.z += wv * v.z; a.w += wv * v.w;
            }
            float is = __ldcg(&g_isd[node]);
            float c0 = g_deg[node] * is * is;
            size_t base = ((size_t)node << 5) + lane;
            float4 m  = __ldcg((const float4*)M + base);
            float4 mp = __ldcg((const float4*)Mp + base);
            float4 o;
            o.x = cA * (m.x + c0 * m.x - is * a.x) + cB * mp.x;
            o.y = cA * (m.y + c0 * m.y - is * a.y) + cB * mp.y;
            o.z = cA * (m.z + c0 * m.z - is * a.z) + cB * mp.z;
            o.w = cA * (m.w + c0 * m.w - is * a.w) + cB * mp.w;
            ((float4*)out)[base] = o;
            if (outb) ((uint2*)outb)[base] = pack4(o);
        }
    }
}

__global__ __launch_bounds__(256, 3) void cgafm_persist_k(const float* __restrict__ gamma,
    const float* __restrict__ asvr, const float* __restrict__ aafm)
{
    __shared__ float sbin[128];
    int tid = threadIdx.x;
    int gtid = blockIdx.x * 256 + tid;
    int stride = gridDim.x * 256;
    int c0 = (gtid & 31) * 4;
    int lane = tid & 31, wid = tid >> 5;
    int gwarp = blockIdx.x * 8 + wid;
    int nwarp = gridDim.x * 8;
    const int NV4 = NH_ / 4;

    if (tid < 128) sbin[tid] = 0.f;
    __syncthreads();
    {
        float a0 = 0.f, a1 = 0.f, a2 = 0.f, a3 = 0.f;
        for (int j = gtid; j < NV4; j += stride) {
            float4 h = ((const float4*)g_h)[j];
            ((float4*)g_X)[j] = make_float4(0.f, 0.f, 0.f, 0.f);
            ((float4*)g_R)[j] = h;
            ((float4*)g_P)[j] = h;
            uint2 pk = pack4(h);
            ((uint2*)g_Pb)[j] = pk;
            ((uint2*)g_hb)[j] = pk;
            a0 += h.x * h.x; a1 += h.y * h.y; a2 += h.z * h.z; a3 += h.w * h.w;
        }
        atomicAdd(&sbin[c0 + 0], a0); atomicAdd(&sbin[c0 + 1], a1);
        atomicAdd(&sbin[c0 + 2], a2); atomicAdd(&sbin[c0 + 3], a3);
    }
    __syncthreads();
    if (tid < 128) { float v = sbin[tid]; if (v != 0.f) atomicAdd(&g_rsA[0][tid], v); }
    gridbar();

    for (int it = 0; it < MAXIT_; it++) {
        if (it > 0) {
            if (tid < 128) sbin[tid] = __ldcg(&g_rsA[it][tid]);
            __syncthreads();
            for (int o = 64; o; o >>= 1) {
                if (tid < o) sbin[tid] = fmaxf(sbin[tid], sbin[tid + o]);
                __syncthreads();
            }
            bool done = sbin[0] < TOL_ * TOL_;
            __syncthreads();
            if (done) break;
            float b0 = __ldcg(&g_rsA[it][c0 + 0]) / (__ldcg(&g_rsA[it - 1][c0 + 0]) + 1e-16f);
            float b1 = __ldcg(&g_rsA[it][c0 + 1]) / (__ldcg(&g_rsA[it - 1][c0 + 1]) + 1e-16f);
            float b2 = __ldcg(&g_rsA[it][c0 + 2]) / (__ldcg(&g_rsA[it - 1][c0 + 2]) + 1e-16f);
            float b3 = __ldcg(&g_rsA[it][c0 + 3]) / (__ldcg(&g_rsA[it - 1][c0 + 3]) + 1e-16f);
            for (int j = gtid; j < NV4; j += stride) {
                float4 r = ((const float4*)g_R)[j];
                float4 p = ((const float4*)g_P)[j];
                p.x = r.x + b0 * p.x; p.y = r.y + b1 * p.y;
                p.z = r.z + b2 * p.z; p.w = r.w + b3 * p.w;
                ((float4*)g_P)[j] = p;
                ((uint2*)g_Pb)[j] = pack4(p);
            }
            gridbar();
        }
        if (tid < 128) sbin[tid] = 0.f;
        __syncthreads();
        {
            float d0 = 0.f, d1 = 0.f, d2 = 0.f, d3 = 0.f;
            for (int wc = gwarp; wc < N_ / 4; wc += nwarp) {
                int nb0 = wc * 4;
#pragma unroll
                for (int k2 = 0; k2 < 4; k2++) {
                    int node = nb0 + k2;
                    int j0 = g_ptr[node], j1 = g_ptr[node + 1];
                    float4 a = make_float4(0.f, 0.f, 0.f, 0.f);
                    for (int j = j0; j < j1; j++) {
                        int nb = g_adj[j]; float wv = g_adjw[j];
                        uint2 raw = __ldcg((const uint2*)g_Pb + ((size_t)nb << 5) + lane);
                        float4 v = unpack4(raw);
                        a.x += wv * v.x; a.y += wv * v.y; a.z += wv * v.z; a.w += wv * v.w;
                    }
                    float cc = 1.f + DT_ * g_deg[node];
                    float4 p = __ldcg((const float4*)g_P + ((size_t)node << 5) + lane);
                    float4 o;
                    o.x = cc * p.x - DT_ * a.x; o.y = cc * p.y - DT_ * a.y;
                    o.z = cc * p.z - DT_ * a.z; o.w = cc * p.w - DT_ * a.w;
                    ((float4*)g_AP)[((size_t)node << 5) + lane] = o;
                    d0 += p.x * o.x; d1 += p.y * o.y; d2 += p.z * o.z; d3 += p.w * o.w;
                }
            }
            atomicAdd(&sbin[lane * 4 + 0], d0); atomicAdd(&sbin[lane * 4 + 1], d1);
            atomicAdd(&sbin[lane * 4 + 2], d2); atomicAdd(&sbin[lane * 4 + 3], d3);
        }
        __syncthreads();
        if (tid < 128) { float v = sbin[tid]; if (v != 0.f) atomicAdd(&g_denA[it][tid], v); }
        gridbar();
        if (tid < 128) sbin[tid] = 0.f;
        __syncthreads();
        {
            float al0 = __ldcg(&g_rsA[it][c0 + 0]) / (__ldcg(&g_denA[it][c0 + 0]) + 1e-16f);
            float al1 = __ldcg(&g_rsA[it][c0 + 1]) / (__ldcg(&g_denA[it][c0 + 1]) + 1e-16f);
            float al2 = __ldcg(&g_rsA[it][c0 + 2]) / (__ldcg(&g_denA[it][c0 + 2]) + 1e-16f);
            float al3 = __ldcg(&g_rsA[it][c0 + 3]) / (__ldcg(&g_denA[it][c0 + 3]) + 1e-16f);
            float s0 = 0.f, s1 = 0.f, s2 = 0.f, s3 = 0.f;
            for (int j = gtid; j < NV4; j += stride) {
                float4 p  = ((const float4*)g_P)[j];
                float4 ap = __ldcg((const float4*)g_AP + j);
                float4 x  = ((const float4*)g_X)[j];
                float4 r  = ((const float4*)g_R)[j];
                x.x += al0 * p.x; x.y += al1 * p.y; x.z += al2 * p.z; x.w += al3 * p.w;
                r.x -= al0 * ap.x; r.y -= al1 * ap.y; r.z -= al2 * ap.z; r.w -= al3 * ap.w;
                ((float4*)g_X)[j] = x;
                ((float4*)g_R)[j] = r;
                s0 += r.x * r.x; s1 += r.y * r.y; s2 += r.z * r.z; s3 += r.w * r.w;
            }
            atomicAdd(&sbin[c0 + 0], s0); atomicAdd(&sbin[c0 + 1], s1);
            atomicAdd(&sbin[c0 + 2], s2); atomicAdd(&sbin[c0 + 3], s3);
        }
        __syncthreads();
        if (tid < 128) { float v = sbin[tid]; if (v != 0.f) atomicAdd(&g_rsA[it + 1][tid], v); }
        gridbar();
    }

    // ---- AFM ----
    for (int n = gtid; n < N_; n += stride)
        g_isd[n] = rsqrtf(fmaxf(g_deg[n], 1e-8f));
    if (blockIdx.x == 0 && tid == 0) {
        float m = gamma[0];
        for (int i = 1; i < 4; i++) m = fmaxf(m, gamma[i]);
        float e[4], s = 0.f;
        for (int i = 0; i < 4; i++) { e[i] = expf(gamma[i] - m); s += e[i]; }
        for (int i = 0; i < 4; i++) g_aq[i] = e[i] / s;
    }
    gridbar();
    for (int j = gtid; j < 2 * E_; j += stride)
        g_adjw2[j] = g_adjw[j] * __ldcg(&g_isd[g_adj[j]]);
    gridbar();
    tildeL_phase(g_h, g_hb, g_h, g_R, g_Rb, 1.f, 0.f);
    gridbar();
    tildeL_phase(g_R, g_Rb, g_h, g_P, g_Pb, 2.f, -1.f);
    gridbar();
    tildeL_phase(g_P, g_Pb, g_R, g_AP, (\
__nv_bfloat162*)0, 2.f, -1.f);
    gridbar();
    float s1 = 1.f / (1.f + expf(-asvr[0]));
    float s2 = 1.f / (1.f + expf(-aafm[0]));
    float a0 = __ldcg(&g_aq[0]), a1 = __ldcg(&g_aq[1]);
    float a2 = __ldcg(&g_aq[2]), a3 = __ldcg(&g_aq[3]);
    for (int j = gtid; j < NV4; j += stride) {
        float4 h = ((const float4*)g_h)[j];
        float4 x  = __ldcg((const float4*)g_X + j);
        float4 r  = __ldcg((const float4*)g_R + j);
        float4 p  = __ldcg((const float4*)g_P + j);
        float4 ap = __ldcg((const float4*)g_AP + j);
        float4 o;
        o.x = h.x + s1 * x.x + s2 * (a0 * h.x + a1 * r.x + a2 * p.x + a3 * ap.x);
        o.y = h.y + s1 * x.y + s2 * (a0 * h.y + a1 * r.y + a2 * p.y + a3 * ap.y);
        o.z = h.z + s1 * x.z + s2 * (a0 * h.z + a1 * r.z + a2 * p.z + a3 * ap.z);
        o.w = h.w + s1 * x.w + s2 * (a0 * h.w + a1 * r.w + a2 * p.w + a3 * ap.w);
        ((float4*)g_F)[j] = o;
    }
}

// ---------------- GAT aggregation ----------------
__global__ void gat1_agg_k(const float* __restrict__ b1)
{
    int node = blockIdx.x * 8 + (threadIdx.x >> 5);
    if (node >= N_) return;
    int lane = threadIdx.x & 31;
    int head = lane >> 2;
    int c0 = (lane & 3) * 2;
    float edv = g_ed1[(size_t)node * 8 + head];
    int j0 = g_inptr[node], j1 = g_inptr[node + 1];
    float m = -3.4e38f, den = 0.f, a0 = 0.f, a1 = 0.f;
    for (int j = j0; j < j1; j++) {
        int s = g_insrc[j];
        float e = g_es1[(size_t)s * 8 + head] + edv;
        e = e >= 0.f ? e : 0.2f * e;
        float mn = fmaxf(m, e);
        float sc = expf(m - mn);
        float p  = expf(e - mn);
        const float* xw = g_xw1 + (size_t)s * 64 + head * 8 + c0;
        den = den * sc + p;
        a0  = a0 * sc + p * xw[0];
        a1  = a1 * sc + p * xw[1];
        m = mn;
    }
    float inv = 1.f / (den + 1e-16f);
    float v0 = a0 * inv + b1[head * 8 + c0];
    float v1 = a1 * inv + b1[head * 8 + c0 + 1];
    v0 = v0 > 0.f ? v0 : expm1f(v0);
    v1 = v1 > 0.f ? v1 : expm1f(v1);
    float* o = g_o1 + (size_t)node * 64 + head * 8 + c0;
    o[0] = v0; o[1] = v1;
}
__global__ void gat2_agg_k(const float* __restrict__ b2, float* __restrict__ out)
{
    int node = blockIdx.x * 16 + (threadIdx.x >> 4);
    if (node >= N_) return;
    int ch = threadIdx.x & 15;
    float edv = g_ed2[node];
    int j0 = g_inptr[node], j1 = g_inptr[node + 1];
    float m = -3.4e38f, den = 0.f, acc = 0.f;
    for (int j = j0; j < j1; j++) {
        int s = g_insrc[j];
        float e = g_es2[s] + edv;
        e = e >= 0.f ? e : 0.2f * e;
        float mn = fmaxf(m, e);
        float sc = expf(m - mn);
        float p  = expf(e - mn);
        den = den * sc + p;
        acc = acc * sc + p * g_xw2[(size_t)s * 16 + ch];
        m = mn;
    }
    out[(size_t)node * 16 + ch] = acc / (den + 1e-16f) + b2[ch];
}

// ---------------- host ----------------
extern "C" void kernel_launch(void* const* d_in, const int* in_sizes, int n_in,
                              void* d_out, int out_size)
{
    const float* x      = (const float*)d_in[0];
    const int*   ei     = (const int*)d_in[1];
    const float* W_in   = (const float*)d_in[2];
    const float* b_in   = (const float*)d_in[3];
    const float* ln_g   = (const float*)d_in[4];
    const float* ln_b   = (const float*)d_in[5];
    const float* W_sh   = (const float*)d_in[6];
    const float* gamma  = (const float*)d_in[7];
    const float* asvr   = (const float*)d_in[8];
    const float* aafm   = (const float*)d_in[9];
    const float* W1     = (const float*)d_in[10];
    const float* a1s    = (const float*)d_in[11];
    const float* a1d    = (const float*)d_in[12];
    const float* b1     = (const float*)d_in[13];
    const float* W2     = (const float*)d_in[14];
    const float* a2s    = (const float*)d_in[15];
    const float* a2d    = (const float*)d_in[16];
    const float* b2     = (const float*)d_in[17];
    const int* row = ei, * col = ei + E_;
    float* out = (float*)d_out;

    const int GB = 391;

    zero3_k<<<196, 256>>>();

    gemm_lnsig_tf32_k<<<GB, 256>>>(x, W_in, b_in, ln_g, ln_b);
    gemm_sheaf_tf32_k<<<GB, 256>>>(W_sh);

    edge_w_k<<<16000, 256>>>(row, col);

    scan2_k<<<1, 1024>>>();
    scatter_adj_k<<<2000, 256>>>(row, col);
    scatter_in_self_k<<<(E_ + N_ + 255) / 256, 256>>>(row, col);

    cgafm_persist_k<<<CGRID_, 256>>>(gamma, asvr, aafm);

    gemm_gat1_tf32_k<<<GB, 256>>>(W1, a1s, a1d);
    gat1_agg_k<<<6250, 256>>>(b1);

    xw2_coeff_k<<<3125, 256>>>(W2, a2s, a2d);
    gat2_agg_k<<<3125, 256>>>(b2, out);
}